// round 1
// baseline (speedup 1.0000x reference)
#include <cuda_runtime.h>
#include <cstdint>

#define N_NODES 100000
#define N_EDGES 800000
#define D 128
#define EPS 1e-5f

#define SCAN_BS 1024
#define NBLK ((N_NODES + SCAN_BS - 1) / SCAN_BS)   // 98

// ---------------- device scratch (no runtime allocation allowed) ----------------
__device__ float g_y[(size_t)N_NODES * D];   // h @ Wl
__device__ float g_z[(size_t)N_NODES * D];   // h @ Wr + b
__device__ float g_h[(size_t)N_NODES * D];   // layer activations
__device__ int   g_deg[N_NODES];
__device__ int   g_rowptr[N_NODES + 1];
__device__ int   g_cursor[N_NODES];
__device__ int   g_eidx[N_EDGES];
__device__ int   g_bsum[NBLK];

typedef unsigned long long ull;

// ---------------- packed f32x2 helpers (FFMA2 path) ----------------
__device__ __forceinline__ void fma2(ull& d, ull a, ull b) {
    asm("fma.rn.f32x2 %0, %1, %2, %3;" : "=l"(d) : "l"(a), "l"(b), "l"(d));
}
__device__ __forceinline__ void add2(ull& d, ull a, ull b) {
    asm("add.rn.f32x2 %0, %1, %2;" : "=l"(d) : "l"(a), "l"(b));
}
__device__ __forceinline__ ull dup2(float x) {
    ull r;
    unsigned u = __float_as_uint(x);
    asm("mov.b64 %0, {%1, %2};" : "=l"(r) : "r"(u), "r"(u));
    return r;
}

// ---------------- CSR build ----------------
__global__ void zero_deg_kernel() {
    int i = blockIdx.x * blockDim.x + threadIdx.x;
    if (i < N_NODES) g_deg[i] = 0;
}

__global__ void count_deg_kernel(const int* __restrict__ dst) {
    int e = blockIdx.x * blockDim.x + threadIdx.x;
    if (e < N_EDGES) atomicAdd(&g_deg[dst[e]], 1);
}

__global__ void scan1_kernel() {
    int t = threadIdx.x;
    int i = blockIdx.x * SCAN_BS + t;
    int v = (i < N_NODES) ? g_deg[i] : 0;
    int lane = t & 31, w = t >> 5;
    int x = v;
#pragma unroll
    for (int d = 1; d < 32; d <<= 1) {
        int y = __shfl_up_sync(0xffffffffu, x, d);
        if (lane >= d) x += y;
    }
    __shared__ int wt[32];
    if (lane == 31) wt[w] = x;
    __syncthreads();
    if (w == 0) {
        int y = wt[lane];
#pragma unroll
        for (int d = 1; d < 32; d <<= 1) {
            int z = __shfl_up_sync(0xffffffffu, y, d);
            if (lane >= d) y += z;
        }
        wt[lane] = y;
    }
    __syncthreads();
    int incl = x + (w > 0 ? wt[w - 1] : 0);
    if (i < N_NODES) g_rowptr[i] = incl - v;       // block-local exclusive
    if (t == SCAN_BS - 1) g_bsum[blockIdx.x] = incl;  // block total
}

__global__ void scan2_kernel() {
    __shared__ int sb[NBLK];
    int t = threadIdx.x;
    if (t < NBLK) sb[t] = g_bsum[t];
    __syncthreads();
    if (t == 0) {
        int run = 0;
        for (int b = 0; b < NBLK; b++) { int v = sb[b]; sb[b] = run; run += v; }
        g_rowptr[N_NODES] = run;   // == N_EDGES
    }
    __syncthreads();
    if (t < NBLK) g_bsum[t] = sb[t];
}

__global__ void scan3_kernel() {
    int i = blockIdx.x * SCAN_BS + threadIdx.x;
    if (i < N_NODES) {
        int r = g_rowptr[i] + g_bsum[blockIdx.x];
        g_rowptr[i] = r;
        g_cursor[i] = r;
    }
}

__global__ void fill_csr_kernel(const int* __restrict__ src, const int* __restrict__ dst) {
    int e = blockIdx.x * blockDim.x + threadIdx.x;
    if (e < N_EDGES) {
        int d = dst[e];
        int pos = atomicAdd(&g_cursor[d], 1);
        g_eidx[pos] = src[e];
    }
}

// ---------------- fused dual GEMM:  Y = A@Wl,  Z = A@Wr + b ----------------
// Block: 64 rows x 256 combined cols.  256 threads: warp tr -> rows tr*8..tr*8+7,
// lane tc -> combined cols tc*8..tc*8+7 (tc<16 => Y, tc>=16 => Z).
#define GEMM_M 64
#define GEMM_SMEM_BYTES ((128 * 256 + GEMM_M * 128) * 4)

__global__ __launch_bounds__(256, 1)
void gemm_kernel(int use_h, const float* __restrict__ Xin,
                 const float* __restrict__ Wl, const float* __restrict__ Wr,
                 const float* __restrict__ bias) {
    extern __shared__ float smem[];
    float* sW = smem;                 // [128][256]
    float* sA = smem + 128 * 256;     // [64][128]

    const float* A = use_h ? g_h : Xin;
    int tid = threadIdx.x;

    // stage combined weights [k][c]: c<128 -> Wl, c>=128 -> Wr
    for (int idx = tid; idx < 128 * 256 / 4; idx += 256) {
        int k  = idx >> 6;       // 64 float4 per 256-float row
        int c4 = idx & 63;
        float4 v;
        if (c4 < 32) v = ((const float4*)Wl)[k * 32 + c4];
        else         v = ((const float4*)Wr)[k * 32 + (c4 - 32)];
        ((float4*)sW)[idx] = v;
    }
    // stage A tile [64][128]
    int rowbase = blockIdx.x * GEMM_M;
    for (int idx = tid; idx < GEMM_M * 128 / 4; idx += 256) {
        int m  = idx >> 5;       // 32 float4 per row
        int c4 = idx & 31;
        int gr = rowbase + m;
        if (gr >= N_NODES) gr = N_NODES - 1;
        ((float4*)sA)[idx] = ((const float4*)A)[(size_t)gr * 32 + c4];
    }
    __syncthreads();

    int tr = tid >> 5;           // warp -> row group
    int tc = tid & 31;           // lane -> col group
    const float* abase = sA + tr * 8 * 128;

    ull acc[8][4];
#pragma unroll
    for (int r = 0; r < 8; r++)
#pragma unroll
        for (int p = 0; p < 4; p++) acc[r][p] = 0ull;

#pragma unroll 8
    for (int k = 0; k < 128; k++) {
        const ull* wk = (const ull*)(sW + k * 256 + tc * 8);
        ull w0 = wk[0], w1 = wk[1], w2 = wk[2], w3 = wk[3];
#pragma unroll
        for (int r = 0; r < 8; r++) {
            ull ad = dup2(abase[r * 128 + k]);
            fma2(acc[r][0], ad, w0);
            fma2(acc[r][1], ad, w1);
            fma2(acc[r][2], ad, w2);
            fma2(acc[r][3], ad, w3);
        }
    }

    // epilogue
    bool isZ = (tc >= 16);
    int c0 = (isZ ? (tc - 16) : tc) * 8;
    float* outp = isZ ? g_z : g_y;
    ull b0 = 0, b1 = 0, b2 = 0, b3 = 0;
    if (isZ) {
        const ull* bp = (const ull*)(bias + c0);
        b0 = bp[0]; b1 = bp[1]; b2 = bp[2]; b3 = bp[3];
    }
#pragma unroll
    for (int r = 0; r < 8; r++) {
        int gr = rowbase + tr * 8 + r;
        if (gr < N_NODES) {
            ull v0 = acc[r][0], v1 = acc[r][1], v2 = acc[r][2], v3 = acc[r][3];
            if (isZ) { add2(v0, v0, b0); add2(v1, v1, b1); add2(v2, v2, b2); add2(v3, v3, b3); }
            ulonglong2* p = (ulonglong2*)(outp + (size_t)gr * D + c0);
            p[0] = make_ulonglong2(v0, v1);
            p[1] = make_ulonglong2(v2, v3);
        }
    }
}

// ---------------- aggregate + epilogue: out = [LN(] P*Y + Z [)+ReLU] ----------------
// One warp per destination node; lane owns 4 consecutive feature channels.
__global__ void agg_kernel(const float* __restrict__ gamma, const float* __restrict__ beta,
                           float* __restrict__ dout, int doLN, int toOut) {
    int node = (blockIdx.x * blockDim.x + threadIdx.x) >> 5;
    int lane = threadIdx.x & 31;
    if (node >= N_NODES) return;

    int s = g_rowptr[node];
    int e = g_rowptr[node + 1];

    float4 acc = make_float4(0.f, 0.f, 0.f, 0.f);
    for (int t = s; t < e; t++) {
        int j = g_eidx[t];
        float4 v = *(const float4*)(g_y + (size_t)j * D + lane * 4);
        acc.x += v.x; acc.y += v.y; acc.z += v.z; acc.w += v.w;
    }
    float inv = 1.0f / fmaxf((float)(e - s), 1.0f);
    float4 z = *(const float4*)(g_z + (size_t)node * D + lane * 4);
    acc.x = acc.x * inv + z.x;
    acc.y = acc.y * inv + z.y;
    acc.z = acc.z * inv + z.z;
    acc.w = acc.w * inv + z.w;

    if (doLN) {
        float sum = acc.x + acc.y + acc.z + acc.w;
#pragma unroll
        for (int o = 16; o; o >>= 1) sum += __shfl_xor_sync(0xffffffffu, sum, o);
        float mu = sum * (1.0f / 128.0f);
        float dx = acc.x - mu, dy = acc.y - mu, dz = acc.z - mu, dw = acc.w - mu;
        float sq = dx * dx + dy * dy + dz * dz + dw * dw;
#pragma unroll
        for (int o = 16; o; o >>= 1) sq += __shfl_xor_sync(0xffffffffu, sq, o);
        float rs = rsqrtf(sq * (1.0f / 128.0f) + EPS);
        float4 g  = *(const float4*)(gamma + lane * 4);
        float4 be = *(const float4*)(beta  + lane * 4);
        acc.x = fmaxf(dx * rs * g.x + be.x, 0.f);
        acc.y = fmaxf(dy * rs * g.y + be.y, 0.f);
        acc.z = fmaxf(dz * rs * g.z + be.z, 0.f);
        acc.w = fmaxf(dw * rs * g.w + be.w, 0.f);
    }

    float* outp = toOut ? dout : g_h;
    *(float4*)(outp + (size_t)node * D + lane * 4) = acc;
}

// ---------------- launch ----------------
extern "C" void kernel_launch(void* const* d_in, const int* in_sizes, int n_in,
                              void* d_out, int out_size) {
    const float* x   = (const float*)d_in[0];
    const int*   src = (const int*)d_in[1];
    const int*   dst = (const int*)d_in[2];
    const float* Wl[3] = { (const float*)d_in[3], (const float*)d_in[6], (const float*)d_in[9]  };
    const float* Wr[3] = { (const float*)d_in[4], (const float*)d_in[7], (const float*)d_in[10] };
    const float* bb[3] = { (const float*)d_in[5], (const float*)d_in[8], (const float*)d_in[11] };
    const float* gm[2] = { (const float*)d_in[12], (const float*)d_in[14] };
    const float* be[2] = { (const float*)d_in[13], (const float*)d_in[15] };
    float* out = (float*)d_out;

    cudaFuncSetAttribute(gemm_kernel, cudaFuncAttributeMaxDynamicSharedMemorySize, GEMM_SMEM_BYTES);

    // CSR build (shared by all 3 layers)
    zero_deg_kernel<<<(N_NODES + 255) / 256, 256>>>();
    count_deg_kernel<<<(N_EDGES + 255) / 256, 256>>>(dst);
    scan1_kernel<<<NBLK, SCAN_BS>>>();
    scan2_kernel<<<1, 128>>>();
    scan3_kernel<<<NBLK, SCAN_BS>>>();
    fill_csr_kernel<<<(N_EDGES + 255) / 256, 256>>>(src, dst);

    int gemm_grid = (N_NODES + GEMM_M - 1) / GEMM_M;   // 1563
    int agg_grid  = (N_NODES * 32 + 255) / 256;        // 12500 (warp per node)

    for (int l = 0; l < 3; l++) {
        gemm_kernel<<<gemm_grid, 256, GEMM_SMEM_BYTES>>>(l == 0 ? 0 : 1, x, Wl[l], Wr[l], bb[l]);
        int doLN  = (l < 2) ? 1 : 0;
        int toOut = (l == 2) ? 1 : 0;
        const float* g = doLN ? gm[l] : gm[0];
        const float* b = doLN ? be[l] : be[0];
        agg_kernel<<<agg_grid, 256>>>(g, b, out, doLN, toOut);
    }
}

// round 4
// speedup vs baseline: 2.1730x; 2.1730x over previous
#include <cuda_runtime.h>
#include <cuda_bf16.h>
#include <cstdint>

#define N_NODES 100000
#define N_EDGES 800000
#define D 128
#define EPS 1e-5f

#define SCAN_BS 1024
#define NBLK ((N_NODES + SCAN_BS - 1) / SCAN_BS)   // 98

#define TILES64 ((N_NODES + 63) / 64)              // 1563
#define A_IMG 16384                                // 64 rows x 128 k x bf16 (swizzled image)
#define B_IMG 65536                                // 256 n x 128 k x bf16 (swizzled image)
#define GEMM_GRID 148

typedef unsigned long long ull;

// ---------------- device scratch ----------------
__device__ float g_y[(size_t)N_NODES * D];   // aggregate operand  (A @ Wl)
__device__ float g_z[(size_t)N_NODES * D];   // self operand       (A @ Wr + b)
__device__ int   g_deg[N_NODES];
__device__ int   g_rowptr[N_NODES + 1];
__device__ int   g_cursor[N_NODES];
__device__ int   g_eidx[N_EDGES];
__device__ int   g_bsum[NBLK];

// pre-swizzled bf16 hi/lo activation tiles (GEMM A operand), 64-row tiles
__device__ __align__(16) unsigned char g_Ah[(size_t)TILES64 * A_IMG];
__device__ __align__(16) unsigned char g_Al[(size_t)TILES64 * A_IMG];
// pre-swizzled bf16 hi/lo combined weights [n=256][k=128] (n<128 -> Wl, n>=128 -> Wr)
__device__ __align__(16) unsigned char g_Bh[3][B_IMG];
__device__ __align__(16) unsigned char g_Bl[3][B_IMG];

// ---------------- helpers ----------------
__device__ __forceinline__ uint32_t swz128(uint32_t off) { return off ^ ((off >> 3) & 0x70); }

// A image: 64 rows, atoms of 8 rows x 128B; atom = (r>>3) + (kcol<<3)
__device__ __forceinline__ uint32_t a_off64(int r, int k0) {
    uint32_t atom  = (uint32_t)((r >> 3) + ((k0 >> 6) << 3));
    uint32_t inner = (uint32_t)((r & 7) * 128 + (k0 & 63) * 2);
    return atom * 1024u + swz128(inner);
}
// B image: 256 n rows; atom = (n>>3) + (kcol<<5)
__device__ __forceinline__ uint32_t b_off(int n, int k0) {
    uint32_t atom  = (uint32_t)((n >> 3) + ((k0 >> 6) << 5));
    uint32_t inner = (uint32_t)((n & 7) * 128 + (k0 & 63) * 2);
    return atom * 1024u + swz128(inner);
}

__device__ __forceinline__ uint32_t s2u(const void* p) {
    uint32_t a;
    asm("{ .reg .u64 t; cvta.to.shared.u64 t, %1; cvt.u32.u64 %0, t; }" : "=r"(a) : "l"(p));
    return a;
}

// split fp32 -> (hi, lo) bf16 pair, pack 4 of each into ull
__device__ __forceinline__ void split4(const float* v, ull& ph, ull& pl) {
    ph = 0; pl = 0;
#pragma unroll
    for (int j = 0; j < 4; j++) {
        __nv_bfloat16 h = __float2bfloat16(v[j]);
        float hv = __bfloat162float(h);
        __nv_bfloat16 l = __float2bfloat16(v[j] - hv);
        ph |= (ull)__bfloat16_as_ushort(h) << (16 * j);
        pl |= (ull)__bfloat16_as_ushort(l) << (16 * j);
    }
}

__device__ __forceinline__ void ldsm4(uint32_t* r, uint32_t addr) {
    asm volatile("ldmatrix.sync.aligned.m8n8.x4.shared.b16 {%0,%1,%2,%3}, [%4];"
                 : "=r"(r[0]), "=r"(r[1]), "=r"(r[2]), "=r"(r[3]) : "r"(addr));
}

#define MMA16816(d, a, b0, b1)                                                        \
    asm volatile("mma.sync.aligned.m16n8k16.row.col.f32.bf16.bf16.f32 "               \
                 "{%0,%1,%2,%3},{%4,%5,%6,%7},{%8,%9},{%0,%1,%2,%3};"                 \
                 : "+f"((d)[0]), "+f"((d)[1]), "+f"((d)[2]), "+f"((d)[3])             \
                 : "r"((a)[0]), "r"((a)[1]), "r"((a)[2]), "r"((a)[3]),                \
                   "r"(b0), "r"(b1))

__device__ __forceinline__ void cpa16(uint32_t sdst, const void* gsrc) {
    asm volatile("cp.async.cg.shared.global [%0], [%1], 16;" :: "r"(sdst), "l"(gsrc) : "memory");
}
__device__ __forceinline__ void cpa_commit() { asm volatile("cp.async.commit_group;" ::: "memory"); }
__device__ __forceinline__ void cpa_wait0()  { asm volatile("cp.async.wait_group 0;" ::: "memory"); }

// ---------------- CSR build ----------------
__global__ void zero_deg_kernel() {
    int i = blockIdx.x * blockDim.x + threadIdx.x;
    if (i < N_NODES) g_deg[i] = 0;
}
__global__ void count_deg_kernel(const int* __restrict__ dst) {
    int e = blockIdx.x * blockDim.x + threadIdx.x;
    if (e < N_EDGES) atomicAdd(&g_deg[dst[e]], 1);
}
__global__ void scan1_kernel() {
    int t = threadIdx.x;
    int i = blockIdx.x * SCAN_BS + t;
    int v = (i < N_NODES) ? g_deg[i] : 0;
    int lane = t & 31, w = t >> 5;
    int x = v;
#pragma unroll
    for (int d = 1; d < 32; d <<= 1) {
        int y = __shfl_up_sync(0xffffffffu, x, d);
        if (lane >= d) x += y;
    }
    __shared__ int wt[32];
    if (lane == 31) wt[w] = x;
    __syncthreads();
    if (w == 0) {
        int y = wt[lane];
#pragma unroll
        for (int d = 1; d < 32; d <<= 1) {
            int z = __shfl_up_sync(0xffffffffu, y, d);
            if (lane >= d) y += z;
        }
        wt[lane] = y;
    }
    __syncthreads();
    int incl = x + (w > 0 ? wt[w - 1] : 0);
    if (i < N_NODES) g_rowptr[i] = incl - v;
    if (t == SCAN_BS - 1) g_bsum[blockIdx.x] = incl;
}
__global__ void scan2_kernel() {
    __shared__ int sb[NBLK];
    int t = threadIdx.x;
    if (t < NBLK) sb[t] = g_bsum[t];
    __syncthreads();
    if (t == 0) {
        int run = 0;
        for (int b = 0; b < NBLK; b++) { int v = sb[b]; sb[b] = run; run += v; }
        g_rowptr[N_NODES] = run;
    }
    __syncthreads();
    if (t < NBLK) g_bsum[t] = sb[t];
}
__global__ void scan3_kernel() {
    int i = blockIdx.x * SCAN_BS + threadIdx.x;
    if (i < N_NODES) {
        int r = g_rowptr[i] + g_bsum[blockIdx.x];
        g_rowptr[i] = r;
        g_cursor[i] = r;
    }
}
__global__ void fill_csr_kernel(const int* __restrict__ src, const int* __restrict__ dst) {
    int e = blockIdx.x * blockDim.x + threadIdx.x;
    if (e < N_EDGES) {
        int d = dst[e];
        int pos = atomicAdd(&g_cursor[d], 1);
        g_eidx[pos] = src[e];
    }
}

// ---------------- operand conversion ----------------
__global__ void convert_x_kernel(const float* __restrict__ x) {
    int node = (blockIdx.x * blockDim.x + threadIdx.x) >> 5;
    int lane = threadIdx.x & 31;
    if (node >= N_NODES) return;
    float4 v = *(const float4*)(x + (size_t)node * D + lane * 4);
    ull ph, pl;
    split4(&v.x, ph, pl);
    size_t base = (size_t)(node >> 6) * A_IMG + a_off64(node & 63, lane * 4);
    *(ull*)(g_Ah + base) = ph;
    *(ull*)(g_Al + base) = pl;
}

__global__ void convert_w_kernel(const float* __restrict__ Wl, const float* __restrict__ Wr, int layer) {
    int idx = blockIdx.x * blockDim.x + threadIdx.x;   // 256 n x 32 k-groups
    if (idx >= 256 * 32) return;
    int n = idx >> 5;
    int k0 = (idx & 31) * 4;
    float v[4];
#pragma unroll
    for (int j = 0; j < 4; j++) {
        int k = k0 + j;
        v[j] = (n < 128) ? Wl[k * 128 + n] : Wr[k * 128 + (n - 128)];
    }
    ull ph, pl;
    split4(v, ph, pl);
    uint32_t off = b_off(n, k0);
    *(ull*)(g_Bh[layer] + off) = ph;
    *(ull*)(g_Bl[layer] + off) = pl;
}

// ---------------- bf16 mma.sync dual GEMM (persistent) ----------------
// smem: Bh[64K] Bl[64K] Abuf0{h,l}[32K] Abuf1{h,l}[32K] = 192KB, 1 CTA/SM
#define SMEM_DYN (196608)

__global__ __launch_bounds__(256, 1)
void mma_gemm_kernel(int layer, const float* __restrict__ bias) {
    extern __shared__ __align__(16) unsigned char dyn[];
    const uint32_t smem_u = s2u(dyn);
    const uint32_t sBh = smem_u;
    const uint32_t sBl = smem_u + 65536;
    const uint32_t sA0 = smem_u + 131072;   // buf i at sA0 + i*32768 ; {h, l=+16384}

    const int tid  = threadIdx.x;
    const int lane = tid & 31;
    const int wid  = tid >> 5;
    const int wm   = wid & 1;        // 0..1 : 32-row group
    const int wn   = wid >> 1;       // 0..3 : 64-col group

    // stage B (hi+lo) once
    {
        const uint4* ph = (const uint4*)(g_Bh[layer]);
        const uint4* pl = (const uint4*)(g_Bl[layer]);
#pragma unroll
        for (int j = 0; j < 16; j++) {
            int idx = tid + j * 256;
            cpa16(sBh + idx * 16, ph + idx);
            cpa16(sBl + idx * 16, pl + idx);
        }
    }
    cpa_commit();

    // prefetch first A tile
    int t0 = blockIdx.x;
    if (t0 < TILES64) {
        const uint4* ph = (const uint4*)(g_Ah + (size_t)t0 * A_IMG);
        const uint4* pl = (const uint4*)(g_Al + (size_t)t0 * A_IMG);
#pragma unroll
        for (int j = 0; j < 4; j++) {
            int idx = tid + j * 256;
            cpa16(sA0 + idx * 16, ph + idx);
            cpa16(sA0 + 16384 + idx * 16, pl + idx);
        }
    }
    cpa_commit();

    // bias pairs for Z half (wn >= 2)
    float2 bz[8];
    if (wn >= 2) {
        int cb = (wn - 2) * 64 + 2 * (lane & 3);
#pragma unroll
        for (int ni = 0; ni < 8; ni++)
            bz[ni] = *(const float2*)(bias + cb + ni * 8);
    }

    const int mat = lane >> 3, rin = lane & 7;

    for (int i = 0; ; i++) {
        int t = blockIdx.x + i * GEMM_GRID;
        if (t >= TILES64) break;

        cpa_wait0();
        __syncthreads();

        // prefetch next tile into other buffer
        int tn = t + GEMM_GRID;
        if (tn < TILES64) {
            uint32_t dstA = sA0 + ((i + 1) & 1) * 32768;
            const uint4* ph = (const uint4*)(g_Ah + (size_t)tn * A_IMG);
            const uint4* pl = (const uint4*)(g_Al + (size_t)tn * A_IMG);
#pragma unroll
            for (int j = 0; j < 4; j++) {
                int idx = tid + j * 256;
                cpa16(dstA + idx * 16, ph + idx);
                cpa16(dstA + 16384 + idx * 16, pl + idx);
            }
        }
        cpa_commit();

        const uint32_t sAh = sA0 + (i & 1) * 32768;
        const uint32_t sAl = sAh + 16384;

        float acc[2][8][4];
#pragma unroll
        for (int mi = 0; mi < 2; mi++)
#pragma unroll
            for (int ni = 0; ni < 8; ni++)
#pragma unroll
                for (int j = 0; j < 4; j++) acc[mi][ni][j] = 0.f;

#pragma unroll
        for (int ks = 0; ks < 8; ks++) {
            uint32_t ah[2][4], al[2][4], bb[4][4];
            uint32_t boff[4];

            // A fragments (hi + lo)
#pragma unroll
            for (int mi = 0; mi < 2; mi++) {
                int r  = wm * 32 + mi * 16 + ((mat & 1) << 3) + rin;
                int kb = ks * 32 + ((mat >> 1) << 4);
                uint32_t off = ((uint32_t)(r >> 3) << 10) + ((uint32_t)(kb >> 7) << 13)
                             + swz128(((uint32_t)(r & 7) << 7) + (kb & 127));
                ldsm4(ah[mi], sAh + off);
                ldsm4(al[mi], sAl + off);
            }
            // B hi fragments
#pragma unroll
            for (int g = 0; g < 4; g++) {
                int n  = wn * 64 + g * 16 + ((mat >> 1) << 3) + rin;
                int kb = ks * 32 + ((mat & 1) << 4);
                boff[g] = ((uint32_t)(n >> 3) << 10) + ((uint32_t)(kb >> 7) << 15)
                        + swz128(((uint32_t)(n & 7) << 7) + (kb & 127));
                ldsm4(bb[g], sBh + boff[g]);
            }
            // Ah*Bh + Al*Bh
#pragma unroll
            for (int mi = 0; mi < 2; mi++)
#pragma unroll
                for (int g = 0; g < 4; g++) {
                    MMA16816(acc[mi][2 * g],     ah[mi], bb[g][0], bb[g][1]);
                    MMA16816(acc[mi][2 * g + 1], ah[mi], bb[g][2], bb[g][3]);
                    MMA16816(acc[mi][2 * g],     al[mi], bb[g][0], bb[g][1]);
                    MMA16816(acc[mi][2 * g + 1], al[mi], bb[g][2], bb[g][3]);
                }
            // B lo fragments, Ah*Bl
#pragma unroll
            for (int g = 0; g < 4; g++) ldsm4(bb[g], sBl + boff[g]);
#pragma unroll
            for (int mi = 0; mi < 2; mi++)
#pragma unroll
                for (int g = 0; g < 4; g++) {
                    MMA16816(acc[mi][2 * g],     ah[mi], bb[g][0], bb[g][1]);
                    MMA16816(acc[mi][2 * g + 1], ah[mi], bb[g][2], bb[g][3]);
                }
        }

        // epilogue: direct stores (Y for wn<2, Z+bias for wn>=2)
        {
            int rbase = t * 64 + wm * 32 + (lane >> 2);
            bool isZ = (wn >= 2);
            int cbase = (isZ ? (wn - 2) : wn) * 64 + 2 * (lane & 3);
            float* obase = isZ ? g_z : g_y;
#pragma unroll
            for (int mi = 0; mi < 2; mi++) {
                int r0 = rbase + mi * 16;
#pragma unroll
                for (int ni = 0; ni < 8; ni++) {
                    int c = cbase + ni * 8;
                    float bx = isZ ? bz[ni].x : 0.f;
                    float by = isZ ? bz[ni].y : 0.f;
                    if (r0 < N_NODES) {
                        float2 v = make_float2(acc[mi][ni][0] + bx, acc[mi][ni][1] + by);
                        *(float2*)(obase + (size_t)r0 * D + c) = v;
                    }
                    if (r0 + 8 < N_NODES) {
                        float2 v = make_float2(acc[mi][ni][2] + bx, acc[mi][ni][3] + by);
                        *(float2*)(obase + (size_t)(r0 + 8) * D + c) = v;
                    }
                }
            }
        }
    }
}

// ---------------- aggregate + epilogue ----------------
__global__ void agg_kernel(const float* __restrict__ gamma, const float* __restrict__ beta,
                           float* __restrict__ dout, int doLN, int toOut) {
    int node = (blockIdx.x * blockDim.x + threadIdx.x) >> 5;
    int lane = threadIdx.x & 31;
    if (node >= N_NODES) return;

    int s = g_rowptr[node];
    int e = g_rowptr[node + 1];

    float4 acc = make_float4(0.f, 0.f, 0.f, 0.f);
    for (int t = s; t < e; t++) {
        int j = g_eidx[t];
        float4 v = *(const float4*)(g_y + (size_t)j * D + lane * 4);
        acc.x += v.x; acc.y += v.y; acc.z += v.z; acc.w += v.w;
    }
    float inv = 1.0f / fmaxf((float)(e - s), 1.0f);
    float4 z = *(const float4*)(g_z + (size_t)node * D + lane * 4);
    acc.x = acc.x * inv + z.x;
    acc.y = acc.y * inv + z.y;
    acc.z = acc.z * inv + z.z;
    acc.w = acc.w * inv + z.w;

    if (doLN) {
        float sum = acc.x + acc.y + acc.z + acc.w;
#pragma unroll
        for (int o = 16; o; o >>= 1) sum += __shfl_xor_sync(0xffffffffu, sum, o);
        float mu = sum * (1.0f / 128.0f);
        float dx = acc.x - mu, dy = acc.y - mu, dz = acc.z - mu, dw = acc.w - mu;
        float sq = dx * dx + dy * dy + dz * dz + dw * dw;
#pragma unroll
        for (int o = 16; o; o >>= 1) sq += __shfl_xor_sync(0xffffffffu, sq, o);
        float rs = rsqrtf(sq * (1.0f / 128.0f) + EPS);
        float4 g  = *(const float4*)(gamma + lane * 4);
        float4 be = *(const float4*)(beta  + lane * 4);
        acc.x = fmaxf(dx * rs * g.x + be.x, 0.f);
        acc.y = fmaxf(dy * rs * g.y + be.y, 0.f);
        acc.z = fmaxf(dz * rs * g.z + be.z, 0.f);
        acc.w = fmaxf(dw * rs * g.w + be.w, 0.f);
    }

    if (toOut) {
        *(float4*)(dout + (size_t)node * D + lane * 4) = acc;
    } else {
        ull ph, pl;
        split4(&acc.x, ph, pl);
        size_t base = (size_t)(node >> 6) * A_IMG + a_off64(node & 63, lane * 4);
        *(ull*)(g_Ah + base) = ph;
        *(ull*)(g_Al + base) = pl;
    }
}

// ---------------- launch ----------------
extern "C" void kernel_launch(void* const* d_in, const int* in_sizes, int n_in,
                              void* d_out, int out_size) {
    const float* x   = (const float*)d_in[0];
    const int*   src = (const int*)d_in[1];
    const int*   dst = (const int*)d_in[2];
    const float* Wl[3] = { (const float*)d_in[3], (const float*)d_in[6], (const float*)d_in[9]  };
    const float* Wr[3] = { (const float*)d_in[4], (const float*)d_in[7], (const float*)d_in[10] };
    const float* bb[3] = { (const float*)d_in[5], (const float*)d_in[8], (const float*)d_in[11] };
    const float* gm[2] = { (const float*)d_in[12], (const float*)d_in[14] };
    const float* be[2] = { (const float*)d_in[13], (const float*)d_in[15] };
    float* out = (float*)d_out;

    cudaFuncSetAttribute(mma_gemm_kernel, cudaFuncAttributeMaxDynamicSharedMemorySize, SMEM_DYN);

    // CSR build
    zero_deg_kernel<<<(N_NODES + 255) / 256, 256>>>();
    count_deg_kernel<<<(N_EDGES + 255) / 256, 256>>>(dst);
    scan1_kernel<<<NBLK, SCAN_BS>>>();
    scan2_kernel<<<1, 128>>>();
    scan3_kernel<<<NBLK, SCAN_BS>>>();
    fill_csr_kernel<<<(N_EDGES + 255) / 256, 256>>>(src, dst);

    // operand conversion
    for (int l = 0; l < 3; l++)
        convert_w_kernel<<<(256 * 32 + 255) / 256, 256>>>(Wl[l], Wr[l], l);
    convert_x_kernel<<<(N_NODES * 32 + 255) / 256, 256>>>(x);

    int agg_grid = (N_NODES * 32 + 255) / 256;

    for (int l = 0; l < 3; l++) {
        mma_gemm_kernel<<<GEMM_GRID, 256, SMEM_DYN>>>(l, bb[l]);
        int doLN  = (l < 2) ? 1 : 0;
        int toOut = (l == 2) ? 1 : 0;
        const float* g = doLN ? gm[l] : gm[0];
        const float* b = doLN ? be[l] : be[0];
        agg_kernel<<<agg_grid, 256>>>(g, b, out, doLN, toOut);
    }
}